// round 1
// baseline (speedup 1.0000x reference)
#include <cuda_runtime.h>

#define N_VEC  16384
#define VOCAB  4096
#define C_DIM  256

#define BM 64
#define BN 128
#define BK 16

// Scratch (device globals: allocation-free per harness rules)
__device__ float g_hflat[N_VEC * C_DIM];      // 16 MB: h transposed to (N, C)
__device__ float g_halfnorm[VOCAB];           // 0.5 * ||e_v||^2
__device__ float g_bestscore[N_VEC];          // max_v (x.e - 0.5||e||^2)
__device__ int   g_bestidx[N_VEC];
__device__ float g_partial[4096];             // per-block sum(h^2) partials

// ---------------------------------------------------------------------------
// 0.5 * ||e_v||^2 for every codebook row. One block per row, 256 threads.
__global__ void halfnorm_kernel(const float* __restrict__ emb) {
    int v = blockIdx.x;
    int t = threadIdx.x;
    float x = emb[v * C_DIM + t];
    float s = x * x;
    __shared__ float sm[8];
    #pragma unroll
    for (int o = 16; o > 0; o >>= 1) s += __shfl_down_sync(0xFFFFFFFFu, s, o);
    if ((t & 31) == 0) sm[t >> 5] = s;
    __syncthreads();
    if (t == 0) {
        float tot = 0.f;
        #pragma unroll
        for (int i = 0; i < 8; i++) tot += sm[i];
        g_halfnorm[v] = 0.5f * tot;
    }
}

// ---------------------------------------------------------------------------
// (B,C,H,W) -> (N,C) transpose with 32x32 smem tiles.
// grid: (sp_tiles=32, c_tiles=8, b=16), block (32,8)
__global__ void transpose_kernel(const float* __restrict__ h) {
    __shared__ float tile[32][33];
    int b = blockIdx.z, ct = blockIdx.y, st = blockIdx.x;
    int c0 = ct * 32, s0 = st * 32;
    int tx = threadIdx.x, ty = threadIdx.y;

    const float* src = h + ((size_t)b * C_DIM + c0) * 1024 + s0;
    #pragma unroll
    for (int i = 0; i < 32; i += 8)
        tile[ty + i][tx] = src[(size_t)(ty + i) * 1024 + tx];   // tile[c][sp]
    __syncthreads();
    float* dst = g_hflat + ((size_t)b * 1024 + s0) * C_DIM + c0;
    #pragma unroll
    for (int i = 0; i < 32; i += 8)
        dst[(size_t)(ty + i) * C_DIM + tx] = tile[tx][ty + i];  // row=sp, col=c
}

// ---------------------------------------------------------------------------
// Deterministic sum(h^2) partials: block k owns elements [k*1024, (k+1)*1024)
__global__ void sumsq_kernel(const float* __restrict__ h) {
    int t = threadIdx.x;
    size_t base = (size_t)blockIdx.x * 1024;
    float s = 0.f;
    #pragma unroll
    for (int i = t; i < 1024; i += 256) { float x = h[base + i]; s += x * x; }
    __shared__ float sm[8];
    #pragma unroll
    for (int o = 16; o > 0; o >>= 1) s += __shfl_down_sync(0xFFFFFFFFu, s, o);
    if ((t & 31) == 0) sm[t >> 5] = s;
    __syncthreads();
    if (t == 0) {
        float tot = 0.f;
        #pragma unroll
        for (int i = 0; i < 8; i++) tot += sm[i];
        g_partial[blockIdx.x] = tot;
    }
}

// ---------------------------------------------------------------------------
// Fused GEMM + argmax. Block: 64 rows x all 4096 codes (32 tiles of 128).
// 256 threads (16x16), micro-tile 4 rows x 8 cols.
__global__ __launch_bounds__(256, 2) void vq_argmax_kernel(const float* __restrict__ emb) {
    __shared__ float As[BK][BM + 4];   // [k][m], padded (stride 68 -> 16B aligned)
    __shared__ float Bs[BK][BN + 4];   // [k][v], padded (stride 132 -> 16B aligned)
    __shared__ float red_s[BM][16];
    __shared__ int   red_i[BM][16];

    int t  = threadIdx.x;
    int tx = t & 15;     // col group: cols tx*8 .. tx*8+7
    int ty = t >> 4;     // row group: rows ty*4 .. ty*4+3
    int m0 = blockIdx.x * BM;

    int lr = t >> 2;          // loader row 0..63
    int lk = (t & 3) * 4;     // loader k offset {0,4,8,12}

    float best[4] = {-1e30f, -1e30f, -1e30f, -1e30f};
    int   bidx[4] = {0, 0, 0, 0};

    for (int v0 = 0; v0 < VOCAB; v0 += BN) {
        float acc[4][8];
        #pragma unroll
        for (int i = 0; i < 4; i++)
            #pragma unroll
            for (int j = 0; j < 8; j++) acc[i][j] = 0.f;

        for (int k0 = 0; k0 < C_DIM; k0 += BK) {
            // A tile: 64 x 16 (one float4 per thread)
            float4 a4 = *(const float4*)&g_hflat[(size_t)(m0 + lr) * C_DIM + k0 + lk];
            As[lk + 0][lr] = a4.x; As[lk + 1][lr] = a4.y;
            As[lk + 2][lr] = a4.z; As[lk + 3][lr] = a4.w;
            // B tile: 128 x 16 (two float4 per thread)
            float4 b4 = *(const float4*)&emb[(size_t)(v0 + lr) * C_DIM + k0 + lk];
            Bs[lk + 0][lr] = b4.x; Bs[lk + 1][lr] = b4.y;
            Bs[lk + 2][lr] = b4.z; Bs[lk + 3][lr] = b4.w;
            float4 b5 = *(const float4*)&emb[(size_t)(v0 + lr + 64) * C_DIM + k0 + lk];
            Bs[lk + 0][lr + 64] = b5.x; Bs[lk + 1][lr + 64] = b5.y;
            Bs[lk + 2][lr + 64] = b5.z; Bs[lk + 3][lr + 64] = b5.w;
            __syncthreads();

            #pragma unroll
            for (int k = 0; k < BK; k++) {
                float a[4], bb[8];
                *(float4*)a        = *(const float4*)&As[k][ty * 4];
                *(float4*)bb       = *(const float4*)&Bs[k][tx * 8];
                *(float4*)(bb + 4) = *(const float4*)&Bs[k][tx * 8 + 4];
                #pragma unroll
                for (int i = 0; i < 4; i++)
                    #pragma unroll
                    for (int j = 0; j < 8; j++)
                        acc[i][j] = fmaf(a[i], bb[j], acc[i][j]);
            }
            __syncthreads();
        }

        // epilogue: score = dot - 0.5||e||^2, keep running argmax.
        // v visited ascending + strict '>' => first-occurrence tie-break.
        #pragma unroll
        for (int j = 0; j < 8; j++) {
            int v = v0 + tx * 8 + j;
            float hn = __ldg(&g_halfnorm[v]);
            #pragma unroll
            for (int i = 0; i < 4; i++) {
                float s = acc[i][j] - hn;
                if (s > best[i]) { best[i] = s; bidx[i] = v; }
            }
        }
    }

    // cross-thread (over tx, ascending v) reduce per row
    #pragma unroll
    for (int i = 0; i < 4; i++) {
        red_s[ty * 4 + i][tx] = best[i];
        red_i[ty * 4 + i][tx] = bidx[i];
    }
    __syncthreads();
    if (t < BM) {
        float bs = red_s[t][0]; int bi = red_i[t][0];
        #pragma unroll
        for (int x = 1; x < 16; x++) {
            if (red_s[t][x] > bs) { bs = red_s[t][x]; bi = red_i[t][x]; }
        }
        g_bestscore[m0 + t] = bs;
        g_bestidx[m0 + t]   = bi;
    }
}

// ---------------------------------------------------------------------------
// z_q gather in (B,C,H,W) layout. block = (b*256 + c), threads over spatial.
__global__ void gather_kernel(const float* __restrict__ emb, float* __restrict__ out) {
    int bc = blockIdx.x;               // 0..4095
    int b = bc >> 8, c = bc & 255;
    int t = threadIdx.x;
    #pragma unroll
    for (int u = 0; u < 4; u++) {
        int sp = t + u * 256;
        int n = b * 1024 + sp;
        out[(size_t)bc * 1024 + sp] = __ldg(&emb[(size_t)g_bestidx[n] * C_DIM + c]);
    }
}

// indices as float32 into out[4194304 ..]
__global__ void indices_kernel(float* __restrict__ out) {
    int n = blockIdx.x * 256 + threadIdx.x;
    out[4194304 + n] = (float)g_bestidx[n];
}

// loss = (sum(h^2) - 2*sum(best_score)) / (N*C), fully deterministic reduce
__global__ void loss_kernel(float* __restrict__ out) {
    __shared__ float sm[256];
    int t = threadIdx.x;
    float s1 = 0.f, s2 = 0.f;
    for (int i = t; i < 4096; i += 256)  s1 += g_partial[i];
    for (int i = t; i < N_VEC; i += 256) s2 += g_bestscore[i];
    sm[t] = s1 - 2.f * s2;
    __syncthreads();
    #pragma unroll
    for (int o = 128; o > 0; o >>= 1) {
        if (t < o) sm[t] += sm[t + o];
        __syncthreads();
    }
    if (t == 0) out[4210688] = sm[0] / 4194304.f;
}

// ---------------------------------------------------------------------------
extern "C" void kernel_launch(void* const* d_in, const int* in_sizes, int n_in,
                              void* d_out, int out_size) {
    const float* h   = (const float*)d_in[0];   // (16,256,32,32) fp32
    const float* emb = (const float*)d_in[1];   // (4096,256) fp32
    float* out = (float*)d_out;

    halfnorm_kernel<<<VOCAB, 256>>>(emb);

    dim3 tgrid(32, 8, 16), tblk(32, 8);
    transpose_kernel<<<tgrid, tblk>>>(h);

    sumsq_kernel<<<4096, 256>>>(h);

    vq_argmax_kernel<<<N_VEC / BM, 256>>>(emb);

    gather_kernel<<<4096, 256>>>(emb, out);
    indices_kernel<<<N_VEC / 256, 256>>>(out);
    loss_kernel<<<1, 256>>>(out);
}